// round 5
// baseline (speedup 1.0000x reference)
#include <cuda_runtime.h>
#include <cuda_bf16.h>
#include <math.h>

// Problem constants (fixed shapes from reference setup_inputs)
#define BB 8
#define NN 1024
#define MM 1024
#define DD 64
#define N_ITER 20

// K_SCALE = (1/eps) * log2(e): exp(z/eps) == exp2(z * K_SCALE)
#define K_SCALE 14.426950408889634f
// log2(1/1024 + 1e-8)
#define LOGMU2 (-9.9999852284f)

#define NBLK 148
#define NTHR 1024
#define MAXROWS 57

// smem floats: Vs[1024] lognu[1024] u[64] a[64] ps[256] then r bf16[57][1024]
#define SMEM_FLOATS (1024 + 1024 + 64 + 64 + 256)
#define SMEM_PERSIST (SMEM_FLOATS * 4 + MAXROWS * MM * 2)

typedef unsigned long long ull;

// ---- packed f32x2 helpers (sm_103a) ----
__device__ __forceinline__ ull pack2(float lo, float hi) {
    ull r;
    asm("mov.b64 %0, {%1, %2};" : "=l"(r) : "f"(lo), "f"(hi));
    return r;
}
__device__ __forceinline__ void unpack2(float& lo, float& hi, ull v) {
    asm("mov.b64 {%0, %1}, %2;" : "=f"(lo), "=f"(hi) : "l"(v));
}
__device__ __forceinline__ ull add2(ull a, ull b) {
    ull r;
    asm("add.rn.f32x2 %0, %1, %2;" : "=l"(r) : "l"(a), "l"(b));
    return r;
}
__device__ __forceinline__ ull fma2(ull a, ull b, ull c) {
    ull r;
    asm("fma.rn.f32x2 %0, %1, %2, %3;" : "=l"(r) : "l"(a), "l"(b), "l"(c));
    return r;
}
__device__ __forceinline__ float ex2(float x) {
    float r;
    asm("ex2.approx.f32 %0, %1;" : "=f"(r) : "f"(x));
    return r;
}

// Scratch (no allocations allowed -> __device__ globals)
__device__ float g_cs[N_ITER][BB * MM];   // per-iteration column sums
__device__ int g_barc[BB * N_ITER];       // per-(batch,iteration) barrier counters
__device__ float g_xn[BB * NN];
__device__ float g_yn[BB * MM];
__device__ float g_lognu2[BB * MM];       // log2(nu + 1e-8)

// ---------------------------------------------------------------------------
// Init (256 blocks x 256 threads = 65536 threads)
// ---------------------------------------------------------------------------
__global__ void sk_init(const float* __restrict__ x, const float* __restrict__ y,
                        const float* __restrict__ w, float* __restrict__ cost) {
    int idx = blockIdx.x * blockDim.x + threadIdx.x;  // 0..65535
    if (idx < BB) cost[idx] = 0.0f;
    if (idx < BB * N_ITER) g_barc[idx] = 0;
    if (idx < BB * NN) {
        const float4* xr = (const float4*)(x + (size_t)idx * DD);
        float s = 0.0f;
#pragma unroll
        for (int k = 0; k < DD / 4; k++) {
            float4 v = xr[k];
            s += v.x * v.x + v.y * v.y + v.z * v.z + v.w * v.w;
        }
        g_xn[idx] = s;
    }
    if (idx < BB * MM) {
        const float4* yr = (const float4*)(y + (size_t)idx * DD);
        float s = 0.0f;
#pragma unroll
        for (int k = 0; k < DD / 4; k++) {
            float4 v = yr[k];
            s += v.x * v.x + v.y * v.y + v.z * v.z + v.w * v.w;
        }
        g_yn[idx] = s;
        g_lognu2[idx] = __log2f(w[idx] + 1e-8f);
    }
    float* csf = &g_cs[0][0];
    for (int i = idx; i < N_ITER * BB * MM; i += 65536) csf[i] = 0.0f;
}

// ---------------------------------------------------------------------------
// GEMM: C = ||x||^2 + ||y||^2 - 2 x.y  (fp32, f32x2 packed FMA)
// ---------------------------------------------------------------------------
__global__ void sk_gemm(const float* __restrict__ x, const float* __restrict__ y,
                        float* __restrict__ C) {
    __shared__ float Xs[DD][68];
    __shared__ float Ys[DD][68];
    int b = blockIdx.z;
    int i0 = blockIdx.y * 64;
    int j0 = blockIdx.x * 64;
    int tid = threadIdx.y * 16 + threadIdx.x;

    const float* xb = x + ((size_t)b * NN + i0) * DD;
    const float* yb = y + ((size_t)b * MM + j0) * DD;
    for (int t = tid; t < 64 * DD; t += 256) {
        int r = t >> 6;
        int d = t & 63;
        Xs[d][r] = xb[r * DD + d];
        Ys[d][r] = yb[r * DD + d];
    }
    __syncthreads();

    int ti = threadIdx.y * 4;
    int tj = threadIdx.x * 4;
    ull acc2[4][2];
#pragma unroll
    for (int r = 0; r < 4; r++) { acc2[r][0] = 0ull; acc2[r][1] = 0ull; }

#pragma unroll
    for (int k = 0; k < DD; k++) {
        float4 a4 = *(const float4*)&Xs[k][ti];
        ulonglong2 b2 = *(const ulonglong2*)&Ys[k][tj];
        ull a0 = pack2(a4.x, a4.x);
        ull a1 = pack2(a4.y, a4.y);
        ull a2_ = pack2(a4.z, a4.z);
        ull a3 = pack2(a4.w, a4.w);
        acc2[0][0] = fma2(a0, b2.x, acc2[0][0]);
        acc2[0][1] = fma2(a0, b2.y, acc2[0][1]);
        acc2[1][0] = fma2(a1, b2.x, acc2[1][0]);
        acc2[1][1] = fma2(a1, b2.y, acc2[1][1]);
        acc2[2][0] = fma2(a2_, b2.x, acc2[2][0]);
        acc2[2][1] = fma2(a2_, b2.y, acc2[2][1]);
        acc2[3][0] = fma2(a3, b2.x, acc2[3][0]);
        acc2[3][1] = fma2(a3, b2.y, acc2[3][1]);
    }

    float yn0 = g_yn[(size_t)b * MM + j0 + tj + 0];
    float yn1 = g_yn[(size_t)b * MM + j0 + tj + 1];
    float yn2 = g_yn[(size_t)b * MM + j0 + tj + 2];
    float yn3 = g_yn[(size_t)b * MM + j0 + tj + 3];
#pragma unroll
    for (int r = 0; r < 4; r++) {
        float a0, a1, a2v, a3;
        unpack2(a0, a1, acc2[r][0]);
        unpack2(a2v, a3, acc2[r][1]);
        float xnv = g_xn[(size_t)b * NN + i0 + ti + r];
        size_t off = ((size_t)b * NN + i0 + ti + r) * MM + j0 + tj;
        float4 o;
        o.x = xnv + yn0 - 2.0f * a0;
        o.y = xnv + yn1 - 2.0f * a1;
        o.z = xnv + yn2 - 2.0f * a2v;
        o.w = xnv + yn3 - 2.0f * a3;
        *(float4*)&C[off] = o;
    }
}

// ---------------------------------------------------------------------------
// Persistent kernel. 148 blocks, 1 per SM. Batch b (8 batches) owns 18-19
// blocks; per-batch barriers only. Block owns nr (53..57) rows of C.
// Phase A is balanced via (row x 256-col quarter) work units.
// ---------------------------------------------------------------------------
__global__ void __launch_bounds__(NTHR, 1)
sk_persist(const float* __restrict__ C, float* __restrict__ pi,
           float* __restrict__ cost) {
    extern __shared__ float sm[];
    float* Vs = sm;                    // [1024]
    float* lognu_sm = sm + 1024;       // [1024]
    float* u_sm = sm + 2048;           // [64]
    float* a_sm = sm + 2112;           // [64]
    float* ps = sm + 2176;             // [256] per-(row,seg) partial sums
    uint2* r_sm = (uint2*)(sm + SMEM_FLOATS);  // [57][256] uint2 = bf16[57][1024]

    const int blk = blockIdx.x;
    const int tid = threadIdx.x;
    const int b = (blk * BB) / NBLK;
    const int lb0 = (b * NBLK + BB - 1) / BB;
    const int lb1 = ((b + 1) * NBLK + BB - 1) / BB;
    const int nb = lb1 - lb0;            // 18 or 19 blocks in this batch
    const int lb = blk - lb0;
    const int rs = (lb * NN) / nb;       // local row start within batch
    const int nr = ((lb + 1) * NN) / nb - rs;  // 53..57
    const int nr4 = nr * 4;
    const int r0 = b * NN + rs;          // global row start

    for (int j = tid; j < MM; j += NTHR) {
        lognu_sm[j] = g_lognu2[b * MM + j];
        Vs[j] = 0.0f;
    }
    if (tid < 64) u_sm[tid] = 0.0f;
    __syncthreads();

    const int warp = tid >> 5, lane = tid & 31;
    const ull nk2 = pack2(-K_SCALE, -K_SCALE);

    for (int it = 0; it < N_ITER; it++) {
        // ---- Phase 0: V update from previous colsum (block-local) ----
        if (it > 0) {
            const float* cs = g_cs[it - 1] + b * MM;
            for (int j = tid; j < MM; j += NTHR)
                Vs[j] += lognu_sm[j] - __log2f(cs[j] + 1e-6f);
            __syncthreads();
        }

        // ---- Phase A: balanced units (row, 256-col quarter) ----
        for (int u4 = warp; u4 < nr4; u4 += 32) {
            int row = u4 >> 2, seg = u4 & 3;
            float uu = u_sm[row];
            ull u2 = pack2(uu, uu);
            const ulonglong2* cr =
                (const ulonglong2*)(C + ((size_t)(r0 + row)) * MM + seg * 256);
            const ulonglong2* vr = (const ulonglong2*)(Vs + seg * 256);
            uint2* rw = r_sm + (size_t)row * 256 + seg * 64;
            float s0 = 0.f, s1 = 0.f, s2 = 0.f, s3 = 0.f;
#pragma unroll
            for (int k = 0; k < 2; k++) {
                int j4 = lane + 32 * k;
                ulonglong2 c = cr[j4];
                ulonglong2 v = vr[j4];
                ull t01 = fma2(c.x, nk2, add2(v.x, u2));
                ull t23 = fma2(c.y, nk2, add2(v.y, u2));
                float e0, e1, e2, e3;
                unpack2(e0, e1, t01);
                unpack2(e2, e3, t23);
                e0 = ex2(e0); e1 = ex2(e1); e2 = ex2(e2); e3 = ex2(e3);
                __nv_bfloat162 b01 = __floats2bfloat162_rn(e0, e1);
                __nv_bfloat162 b23 = __floats2bfloat162_rn(e2, e3);
                uint2 st;
                st.x = *reinterpret_cast<unsigned*>(&b01);
                st.y = *reinterpret_cast<unsigned*>(&b23);
                rw[j4] = st;
                s0 += e0; s1 += e1; s2 += e2; s3 += e3;
            }
            float s = (s0 + s1) + (s2 + s3);
#pragma unroll
            for (int o = 16; o; o >>= 1) s += __shfl_xor_sync(0xFFFFFFFFu, s, o);
            if (lane == 0) ps[u4] = s;
        }
        __syncthreads();

        // ---- U update (one thread per row) ----
        if (tid < nr) {
            float s = (ps[tid * 4] + ps[tid * 4 + 1]) +
                      (ps[tid * 4 + 2] + ps[tid * 4 + 3]);
            float lg = __log2f(s + 1e-6f);
            u_sm[tid] += LOGMU2 - lg;
            a_sm[tid] = ex2(LOGMU2 - lg);  // exp((U'-U)/eps)
        }
        __syncthreads();

        // ---- Phase B: column partials (2 row-groups x 512 col-pair threads) --
        {
            int grp = tid >> 9, j2 = tid & 511;
            int nrh = nr >> 1;
            int p0 = grp ? nrh : 0, p1 = grp ? nr : nrh;
            float ax = 0.f, ay = 0.f;
            const __nv_bfloat162* rb = (const __nv_bfloat162*)r_sm;
            for (int rl = p0; rl < p1; rl++) {
                float2 rv = __bfloat1622float2(rb[(size_t)rl * 512 + j2]);
                float a = a_sm[rl];
                ax = fmaf(rv.x, a, ax);
                ay = fmaf(rv.y, a, ay);
            }
            float* cso = g_cs[it] + b * MM;
            atomicAdd(&cso[2 * j2 + 0], ax);
            atomicAdd(&cso[2 * j2 + 1], ay);
        }

        // ---- per-batch barrier ----
        __threadfence();
        __syncthreads();
        if (tid == 0) {
            int slot = b * N_ITER + it;
            atomicAdd(&g_barc[slot], 1);
            while (*((volatile int*)&g_barc[slot]) < nb) __nanosleep(32);
        }
        __syncthreads();
    }

    // ---- Final V update ----
    {
        const float* cs = g_cs[N_ITER - 1] + b * MM;
        for (int j = tid; j < MM; j += NTHR)
            Vs[j] += lognu_sm[j] - __log2f(cs[j] + 1e-6f);
    }
    __syncthreads();

    // ---- Final pi + cost (balanced units) ----
    for (int u4 = warp; u4 < nr4; u4 += 32) {
        int row = u4 >> 2, seg = u4 & 3;
        float uu = u_sm[row];
        ull u2 = pack2(uu, uu);
        const float4* cf = (const float4*)(C + ((size_t)(r0 + row)) * MM + seg * 256);
        const ulonglong2* vr = (const ulonglong2*)(Vs + seg * 256);
        float4* pr = (float4*)(pi + ((size_t)(r0 + row)) * MM + seg * 256);
        float s = 0.f;
#pragma unroll
        for (int k = 0; k < 2; k++) {
            int j4 = lane + 32 * k;
            float4 c = cf[j4];
            ulonglong2 v = vr[j4];
            ull c01 = pack2(c.x, c.y);
            ull c23 = pack2(c.z, c.w);
            ull t01 = fma2(c01, nk2, add2(v.x, u2));
            ull t23 = fma2(c23, nk2, add2(v.y, u2));
            float e0, e1, e2, e3;
            unpack2(e0, e1, t01);
            unpack2(e2, e3, t23);
            float4 p;
            p.x = ex2(e0); p.y = ex2(e1); p.z = ex2(e2); p.w = ex2(e3);
            pr[j4] = p;
            s = fmaf(p.x, c.x, s);
            s = fmaf(p.y, c.y, s);
            s = fmaf(p.z, c.z, s);
            s = fmaf(p.w, c.w, s);
        }
#pragma unroll
        for (int o = 16; o; o >>= 1) s += __shfl_xor_sync(0xFFFFFFFFu, s, o);
        if (lane == 0) atomicAdd(&cost[b], s);
    }
}

// ---------------------------------------------------------------------------
// Launch. Output: [0,8) cost | [8, 8+B*N*M) pi | then C
// ---------------------------------------------------------------------------
extern "C" void kernel_launch(void* const* d_in, const int* in_sizes, int n_in,
                              void* d_out, int out_size) {
    const float* x = (const float*)d_in[0];
    const float* y = (const float*)d_in[1];
    const float* w = (const float*)d_in[2];
    float* cost = (float*)d_out;
    float* pi = cost + BB;
    float* C = pi + (size_t)BB * NN * MM;

    cudaFuncSetAttribute(sk_persist, cudaFuncAttributeMaxDynamicSharedMemorySize,
                         SMEM_PERSIST);

    sk_init<<<256, 256>>>(x, y, w, cost);
    sk_gemm<<<dim3(MM / 64, NN / 64, BB), dim3(16, 16)>>>(x, y, C);
    sk_persist<<<NBLK, NTHR, SMEM_PERSIST>>>(C, pi, cost);
}

// round 6
// speedup vs baseline: 1.2663x; 1.2663x over previous
#include <cuda_runtime.h>
#include <cuda_bf16.h>
#include <math.h>

// Problem constants (fixed shapes from reference setup_inputs)
#define BB 8
#define NN 1024
#define MM 1024
#define DD 64
#define N_ITER 20

// K_SCALE = (1/eps) * log2(e): exp(z/eps) == exp2(z * K_SCALE)
#define K_SCALE 14.426950408889634f
// log2(1/1024 + 1e-8)
#define LOGMU2 (-9.9999852284f)

#define NBLK 148
#define NTHR 1024
#define MAXROWS 57

// smem floats: Vs[1024] lognu[1024] a[64] | r bf16[MAXROWS][1024]
#define SMEM_FLOATS (1024 + 1024 + 64)
#define SMEM_PERSIST (SMEM_FLOATS * 4 + MAXROWS * MM * 2)

typedef unsigned long long ull;

// ---- packed f32x2 helpers (sm_103a) ----
__device__ __forceinline__ ull pack2(float lo, float hi) {
    ull r;
    asm("mov.b64 %0, {%1, %2};" : "=l"(r) : "f"(lo), "f"(hi));
    return r;
}
__device__ __forceinline__ void unpack2(float& lo, float& hi, ull v) {
    asm("mov.b64 {%0, %1}, %2;" : "=f"(lo), "=f"(hi) : "l"(v));
}
__device__ __forceinline__ ull add2(ull a, ull b) {
    ull r;
    asm("add.rn.f32x2 %0, %1, %2;" : "=l"(r) : "l"(a), "l"(b));
    return r;
}
__device__ __forceinline__ ull fma2(ull a, ull b, ull c) {
    ull r;
    asm("fma.rn.f32x2 %0, %1, %2, %3;" : "=l"(r) : "l"(a), "l"(b), "l"(c));
    return r;
}
__device__ __forceinline__ float ex2(float x) {
    float r;
    asm("ex2.approx.f32 %0, %1;" : "=f"(r) : "f"(x));
    return r;
}

// Scratch (no allocations allowed -> __device__ globals)
__device__ float g_cs[N_ITER][BB * MM];   // per-iteration column sums
__device__ int g_barc[BB * N_ITER];       // per-(batch,iteration) barrier counters
__device__ float g_lognu2[BB * MM];       // log2(nu + 1e-8)

// ---------------------------------------------------------------------------
// Init: zero cs/barc/cost, compute lognu. 64 blocks x 256 threads.
// ---------------------------------------------------------------------------
__global__ void sk_init(const float* __restrict__ w, float* __restrict__ cost) {
    int idx = blockIdx.x * blockDim.x + threadIdx.x;  // 0..16383
    if (idx < BB) cost[idx] = 0.0f;
    if (idx < BB * N_ITER) g_barc[idx] = 0;
    if (idx < BB * MM) g_lognu2[idx] = __log2f(w[idx] + 1e-8f);
    float4* csf = (float4*)&g_cs[0][0];
    const float4 z = {0.f, 0.f, 0.f, 0.f};
    for (int i = idx; i < N_ITER * BB * MM / 4; i += 16384) csf[i] = z;
}

// ---------------------------------------------------------------------------
// GEMM: C = ||x||^2 + ||y||^2 - 2 x.y. Norms computed from smem tiles
// (full D=64 is resident), no separate norm pass needed.
// ---------------------------------------------------------------------------
__global__ void sk_gemm(const float* __restrict__ x, const float* __restrict__ y,
                        float* __restrict__ C) {
    __shared__ float Xs[DD][68];
    __shared__ float Ys[DD][68];
    __shared__ float xn_sm[64];
    __shared__ float yn_sm[64];
    int b = blockIdx.z;
    int i0 = blockIdx.y * 64;
    int j0 = blockIdx.x * 64;
    int tid = threadIdx.y * 16 + threadIdx.x;

    const float* xb = x + ((size_t)b * NN + i0) * DD;
    const float* yb = y + ((size_t)b * MM + j0) * DD;
    for (int t = tid; t < 64 * DD; t += 256) {
        int r = t >> 6;
        int d = t & 63;
        Xs[d][r] = xb[r * DD + d];
        Ys[d][r] = yb[r * DD + d];
    }
    __syncthreads();

    // Row/col norms from smem (threads 0..63: x rows, 64..127: y rows)
    if (tid < 128) {
        int r = tid & 63;
        float s = 0.0f;
        if (tid < 64) {
#pragma unroll 8
            for (int d = 0; d < DD; d++) { float v = Xs[d][r]; s += v * v; }
            xn_sm[r] = s;
        } else {
#pragma unroll 8
            for (int d = 0; d < DD; d++) { float v = Ys[d][r]; s += v * v; }
            yn_sm[r] = s;
        }
    }

    int ti = threadIdx.y * 4;
    int tj = threadIdx.x * 4;
    ull acc2[4][2];
#pragma unroll
    for (int r = 0; r < 4; r++) { acc2[r][0] = 0ull; acc2[r][1] = 0ull; }

#pragma unroll
    for (int k = 0; k < DD; k++) {
        float4 a4 = *(const float4*)&Xs[k][ti];
        ulonglong2 b2 = *(const ulonglong2*)&Ys[k][tj];
        ull a0 = pack2(a4.x, a4.x);
        ull a1 = pack2(a4.y, a4.y);
        ull a2_ = pack2(a4.z, a4.z);
        ull a3 = pack2(a4.w, a4.w);
        acc2[0][0] = fma2(a0, b2.x, acc2[0][0]);
        acc2[0][1] = fma2(a0, b2.y, acc2[0][1]);
        acc2[1][0] = fma2(a1, b2.x, acc2[1][0]);
        acc2[1][1] = fma2(a1, b2.y, acc2[1][1]);
        acc2[2][0] = fma2(a2_, b2.x, acc2[2][0]);
        acc2[2][1] = fma2(a2_, b2.y, acc2[2][1]);
        acc2[3][0] = fma2(a3, b2.x, acc2[3][0]);
        acc2[3][1] = fma2(a3, b2.y, acc2[3][1]);
    }
    __syncthreads();

    float yn0 = yn_sm[tj + 0];
    float yn1 = yn_sm[tj + 1];
    float yn2 = yn_sm[tj + 2];
    float yn3 = yn_sm[tj + 3];
#pragma unroll
    for (int r = 0; r < 4; r++) {
        float a0, a1, a2v, a3;
        unpack2(a0, a1, acc2[r][0]);
        unpack2(a2v, a3, acc2[r][1]);
        float xnv = xn_sm[ti + r];
        size_t off = ((size_t)b * NN + i0 + ti + r) * MM + j0 + tj;
        float4 o;
        o.x = xnv + yn0 - 2.0f * a0;
        o.y = xnv + yn1 - 2.0f * a1;
        o.z = xnv + yn2 - 2.0f * a2v;
        o.w = xnv + yn3 - 2.0f * a3;
        *(float4*)&C[off] = o;
    }
}

// ---------------------------------------------------------------------------
// Phase A row: r_j = exp2(C_j*(-K) + v_j + u), rowsum -> U update + a.
// Warp-collective full-row walk (8x unroll -> 8 outstanding 16B loads).
// ---------------------------------------------------------------------------
__device__ __forceinline__ void rowA(const float* __restrict__ Crow,
                                     const float* __restrict__ Vs,
                                     uint2* __restrict__ rw,
                                     int lane, float& u, float* a_slot) {
    const ull u2 = pack2(u, u);
    const ull nk2 = pack2(-K_SCALE, -K_SCALE);
    const ulonglong2* cr = (const ulonglong2*)Crow;
    const ulonglong2* vr = (const ulonglong2*)Vs;
    float s0 = 0.f, s1 = 0.f, s2 = 0.f, s3 = 0.f;
#pragma unroll
    for (int k = 0; k < MM / 128; k++) {
        int j4 = lane + 32 * k;
        ulonglong2 c = cr[j4];
        ulonglong2 v = vr[j4];
        ull t01 = fma2(c.x, nk2, add2(v.x, u2));
        ull t23 = fma2(c.y, nk2, add2(v.y, u2));
        float e0, e1, e2, e3;
        unpack2(e0, e1, t01);
        unpack2(e2, e3, t23);
        e0 = ex2(e0); e1 = ex2(e1); e2 = ex2(e2); e3 = ex2(e3);
        __nv_bfloat162 b01 = __floats2bfloat162_rn(e0, e1);
        __nv_bfloat162 b23 = __floats2bfloat162_rn(e2, e3);
        uint2 st;
        st.x = *reinterpret_cast<unsigned*>(&b01);
        st.y = *reinterpret_cast<unsigned*>(&b23);
        rw[j4] = st;
        s0 += e0; s1 += e1; s2 += e2; s3 += e3;
    }
    float s = (s0 + s1) + (s2 + s3);
#pragma unroll
    for (int o = 16; o; o >>= 1) s += __shfl_xor_sync(0xFFFFFFFFu, s, o);
    float unew = 0.f;
    if (lane == 0) {
        float lg = __log2f(s + 1e-6f);
        unew = u + LOGMU2 - lg;
        *a_slot = ex2(LOGMU2 - lg);  // exp((U'-U)/eps)
    }
    u = __shfl_sync(0xFFFFFFFFu, unew, 0);
}

// ---------------------------------------------------------------------------
// Final row: pi = exp2(C*(-K) + v + u), cost partial = sum pi*C
// ---------------------------------------------------------------------------
__device__ __forceinline__ void rowFinal(const float* __restrict__ Crow,
                                         const float* __restrict__ Vs,
                                         float* __restrict__ pirow,
                                         int lane, float u, float* cost_b) {
    const ull u2 = pack2(u, u);
    const ull nk2 = pack2(-K_SCALE, -K_SCALE);
    const float4* cf = (const float4*)Crow;
    const ulonglong2* vr = (const ulonglong2*)Vs;
    float4* pr = (float4*)pirow;
    float s = 0.f;
#pragma unroll
    for (int k = 0; k < MM / 128; k++) {
        int j4 = lane + 32 * k;
        float4 c = cf[j4];
        ulonglong2 v = vr[j4];
        ull c01 = pack2(c.x, c.y);
        ull c23 = pack2(c.z, c.w);
        ull t01 = fma2(c01, nk2, add2(v.x, u2));
        ull t23 = fma2(c23, nk2, add2(v.y, u2));
        float e0, e1, e2, e3;
        unpack2(e0, e1, t01);
        unpack2(e2, e3, t23);
        float4 p;
        p.x = ex2(e0); p.y = ex2(e1); p.z = ex2(e2); p.w = ex2(e3);
        pr[j4] = p;
        s = fmaf(p.x, c.x, s);
        s = fmaf(p.y, c.y, s);
        s = fmaf(p.z, c.z, s);
        s = fmaf(p.w, c.w, s);
    }
#pragma unroll
    for (int o = 16; o; o >>= 1) s += __shfl_xor_sync(0xFFFFFFFFu, s, o);
    if (lane == 0) atomicAdd(cost_b, s);
}

// ---------------------------------------------------------------------------
// Persistent kernel: 148 blocks, 1/SM. Each block belongs to exactly ONE
// batch (18-19 blocks per batch, 53-57 rows per block); per-batch barriers.
// ---------------------------------------------------------------------------
__global__ void __launch_bounds__(NTHR, 1)
sk_persist(const float* __restrict__ C, float* __restrict__ pi,
           float* __restrict__ cost) {
    extern __shared__ float sm[];
    float* Vs = sm;                    // [1024]
    float* lognu_sm = sm + 1024;       // [1024]
    float* a_sm = sm + 2048;           // [64]
    uint2* r_sm = (uint2*)(sm + SMEM_FLOATS);  // [MAXROWS][256] = bf16[57][1024]

    const int blk = blockIdx.x;
    const int tid = threadIdx.x;
    const int b = (blk * BB) / NBLK;
    const int lb0 = (b * NBLK + BB - 1) / BB;
    const int lb1 = ((b + 1) * NBLK + BB - 1) / BB;
    const int nb = lb1 - lb0;                  // blocks in this batch (18/19)
    const int lb = blk - lb0;
    const int rs = (lb * NN) / nb;
    const int nr = ((lb + 1) * NN) / nb - rs;  // 53..57
    const int r0 = b * NN + rs;                // global start row

    for (int j = tid; j < MM; j += NTHR) {
        lognu_sm[j] = g_lognu2[b * MM + j];
        Vs[j] = 0.0f;
    }
    __syncthreads();

    const int warp = tid >> 5, lane = tid & 31;
    const bool has1 = (32 + warp) < nr;
    float u0 = 0.0f, u1 = 0.0f;

    // Phase-B mapping: 2 row-groups x 512 col-pair threads
    const int grp = tid >> 9;
    const int j2 = tid & 511;
    const int nrh = nr >> 1;
    const int p0 = grp ? nrh : 0;
    const int p1 = grp ? nr : nrh;

    for (int it = 0; it < N_ITER; it++) {
        // ---- Phase 0: V update from previous colsum ----
        if (it > 0) {
            const float* cs = g_cs[it - 1] + b * MM;
            for (int j = tid; j < MM; j += NTHR)
                Vs[j] += lognu_sm[j] - __log2f(cs[j] + 1e-6f);
            __syncthreads();
        }

        // ---- Phase A: warp-per-row, up to 2 rows/warp ----
        rowA(C + (size_t)(r0 + warp) * MM, Vs, r_sm + (size_t)warp * 256,
             lane, u0, a_sm + warp);
        if (has1)
            rowA(C + (size_t)(r0 + 32 + warp) * MM, Vs,
                 r_sm + (size_t)(warp + 32) * 256, lane, u1, a_sm + warp + 32);
        __syncthreads();

        // ---- Phase B: column partials from bf16 r, scaled by a ----
        {
            float ax = 0.f, ay = 0.f;
            const __nv_bfloat162* rb = (const __nv_bfloat162*)r_sm;
            for (int rl = p0; rl < p1; rl++) {
                float2 rv = __bfloat1622float2(rb[(size_t)rl * 512 + j2]);
                float a = a_sm[rl];
                ax = fmaf(rv.x, a, ax);
                ay = fmaf(rv.y, a, ay);
            }
            float* cso = g_cs[it] + b * MM;
            atomicAdd(&cso[2 * j2 + 0], ax);
            atomicAdd(&cso[2 * j2 + 1], ay);
        }

        // ---- per-batch barrier ----
        __threadfence();
        __syncthreads();
        if (tid == 0) {
            int slot = b * N_ITER + it;
            atomicAdd(&g_barc[slot], 1);
            while (*((volatile int*)&g_barc[slot]) < nb) __nanosleep(32);
        }
        __syncthreads();
    }

    // ---- Final V update ----
    {
        const float* cs = g_cs[N_ITER - 1] + b * MM;
        for (int j = tid; j < MM; j += NTHR)
            Vs[j] += lognu_sm[j] - __log2f(cs[j] + 1e-6f);
    }
    __syncthreads();

    // ---- Final pi + cost ----
    rowFinal(C + (size_t)(r0 + warp) * MM, Vs, pi + (size_t)(r0 + warp) * MM,
             lane, u0, &cost[b]);
    if (has1)
        rowFinal(C + (size_t)(r0 + 32 + warp) * MM, Vs,
                 pi + (size_t)(r0 + 32 + warp) * MM, lane, u1, &cost[b]);
}

// ---------------------------------------------------------------------------
// Launch. Output: [0,8) cost | [8, 8+B*N*M) pi | then C
// ---------------------------------------------------------------------------
extern "C" void kernel_launch(void* const* d_in, const int* in_sizes, int n_in,
                              void* d_out, int out_size) {
    const float* x = (const float*)d_in[0];
    const float* y = (const float*)d_in[1];
    const float* w = (const float*)d_in[2];
    float* cost = (float*)d_out;
    float* pi = cost + BB;
    float* C = pi + (size_t)BB * NN * MM;

    cudaFuncSetAttribute(sk_persist, cudaFuncAttributeMaxDynamicSharedMemorySize,
                         SMEM_PERSIST);

    sk_init<<<64, 256>>>(w, cost);
    sk_gemm<<<dim3(MM / 64, NN / 64, BB), dim3(16, 16)>>>(x, y, C);
    sk_persist<<<NBLK, NTHR, SMEM_PERSIST>>>(C, pi, cost);
}